// round 1
// baseline (speedup 1.0000x reference)
#include <cuda_runtime.h>

#define IMG_H 512
#define IMG_W 512
#define RPB   64          // rows per block
#define KRAD  15
#define INV_KK (1.0f/961.0f)

__device__ double g_acc[3];   // [0]=sum(weit*bce), [1]=sum(p*t*weit), [2]=sum((p+t)*weit)

__global__ void init_acc_kernel() {
    g_acc[0] = 0.0; g_acc[1] = 0.0; g_acc[2] = 0.0;
}

__global__ __launch_bounds__(512) void wiou_bce_main(
    const float* __restrict__ X,   // logits
    const float* __restrict__ T)   // targets
{
    __shared__ float Psh[IMG_W];
    __shared__ float wsum[16];
    __shared__ float red[16 * 3];

    const int x    = threadIdx.x;          // column 0..511
    const int lane = x & 31;
    const int wid  = x >> 5;

    const int bpi  = IMG_H / RPB;          // blocks per image = 8
    const int n    = blockIdx.x / bpi;
    const int y0   = (blockIdx.x % bpi) * RPB;

    const float* Tn = T + (size_t)n * IMG_H * IMG_W;
    const float* Xn = X + (size_t)n * IMG_H * IMG_W;

    // Prologue: vertical running sum over rows [y0-15, y0+14] (zero-padded)
    float vs = 0.f;
    #pragma unroll
    for (int k = -KRAD; k < KRAD; ++k) {
        int yy = y0 + k;
        if (yy >= 0 && yy < IMG_H) vs += Tn[yy * IMG_W + x];
    }

    float a0 = 0.f, a1 = 0.f, a2 = 0.f;

    for (int y = y0; y < y0 + RPB; ++y) {
        // extend window to include row y+15 -> vs = sum rows [y-15, y+15]
        int ya = y + KRAD;
        if (ya < IMG_H) vs += Tn[ya * IMG_W + x];

        // ---- block-wide inclusive prefix scan of vs across 512 columns ----
        float v = vs;
        #pragma unroll
        for (int off = 1; off < 32; off <<= 1) {
            float nb = __shfl_up_sync(0xffffffffu, v, off);
            if (lane >= off) v += nb;
        }
        if (lane == 31) wsum[wid] = v;
        __syncthreads();
        if (wid == 0) {
            float w = (lane < 16) ? wsum[lane] : 0.f;
            #pragma unroll
            for (int off = 1; off < 16; off <<= 1) {
                float nb = __shfl_up_sync(0xffffffffu, w, off);
                if (lane >= off) w += nb;
            }
            if (lane < 16) wsum[lane] = w;
        }
        __syncthreads();
        float P = v + (wid ? wsum[wid - 1] : 0.f);
        Psh[x] = P;
        __syncthreads();

        float hi = Psh[min(x + KRAD, IMG_W - 1)];
        float lo = (x >= KRAD + 1) ? Psh[x - KRAD - 1] : 0.f;
        float ws = hi - lo;                      // 31x31 box sum (zero-padded)

        // ---- fused elementwise ----
        float t   = Tn[y * IMG_W + x];           // L1 hit (loaded 15 iters ago)
        float xin = Xn[y * IMG_W + x];

        float box  = ws * INV_KK;
        float weit = 1.0f + 5.0f * fabsf(box - t);

        float e    = __expf(-fabsf(xin));
        float l1p  = log1pf(e);
        float ls_p = fminf(xin, 0.f)  - l1p;     // log sigmoid(x)
        float ls_n = fminf(-xin, 0.f) - l1p;     // log sigmoid(-x)
        float bce  = -(t * ls_p + (1.f - t) * ls_n);
        float p    = 1.0f / (1.0f + __expf(-xin));

        a0 += weit * bce;
        a1 += p * t * weit;
        a2 += (p + t) * weit;

        // retire row y-15 -> vs = sum rows [y-14, y+15]
        int ys = y - KRAD;
        if (ys >= 0) vs -= Tn[ys * IMG_W + x];   // L1 hit

        __syncthreads();   // protect Psh/wsum reuse next iteration
    }

    // ---- block reduction of the 3 accumulators ----
    #pragma unroll
    for (int off = 16; off > 0; off >>= 1) {
        a0 += __shfl_down_sync(0xffffffffu, a0, off);
        a1 += __shfl_down_sync(0xffffffffu, a1, off);
        a2 += __shfl_down_sync(0xffffffffu, a2, off);
    }
    if (lane == 0) { red[wid*3+0] = a0; red[wid*3+1] = a1; red[wid*3+2] = a2; }
    __syncthreads();
    if (x == 0) {
        float s0 = 0.f, s1 = 0.f, s2 = 0.f;
        #pragma unroll
        for (int i = 0; i < 16; ++i) { s0 += red[i*3]; s1 += red[i*3+1]; s2 += red[i*3+2]; }
        atomicAdd(&g_acc[0], (double)s0);
        atomicAdd(&g_acc[1], (double)s1);
        atomicAdd(&g_acc[2], (double)s2);
    }
}

__global__ void finalize_kernel(float* out, double inv_count) {
    double wbce  = g_acc[0] * inv_count;
    double inter = g_acc[1];
    double total = g_acc[2];
    double uni   = total - inter;
    double wiou  = 1.0 - (inter + 1.0) / (uni + 1.0);
    out[0] = (float)(wbce + wiou);
}

extern "C" void kernel_launch(void* const* d_in, const int* in_sizes, int n_in,
                              void* d_out, int out_size) {
    const float* X = (const float*)d_in[0];   // inputs (logits)
    const float* T = (const float*)d_in[1];   // targets
    float* out = (float*)d_out;

    const int n_elem = in_sizes[0];
    const int imgs   = n_elem / (IMG_H * IMG_W);
    const int bpi    = IMG_H / RPB;

    init_acc_kernel<<<1, 1>>>();
    wiou_bce_main<<<imgs * bpi, 512>>>(X, T);
    finalize_kernel<<<1, 1>>>(out, 1.0 / (double)n_elem);
}

// round 2
// speedup vs baseline: 2.8805x; 2.8805x over previous
#include <cuda_runtime.h>

#define IMG_H 512
#define IMG_W 512
#define RPB   32            // rows per block strip
#define KRAD  15
#define INV_KK (1.0f/961.0f)
#define TPB   128           // threads per block; each owns 4 columns (128*4 = 512)
#define MAXB  8192

__device__ float g_part[3 * MAXB];   // SoA block partials

__global__ __launch_bounds__(TPB) void wiou_bce_main(
    const float* __restrict__ X,   // logits
    const float* __restrict__ T)   // targets
{
    __shared__ float Psh[2][IMG_W];   // block-wide prefix of vertical sums (double-buffered)
    __shared__ float wsum[2][4];      // per-warp scan totals
    __shared__ float red[4][3];

    const int tid  = threadIdx.x;          // 0..127
    const int lane = tid & 31;
    const int wid  = tid >> 5;             // 0..3
    const int c0   = tid << 2;             // first column owned (multiple of 4)

    const int bpi  = IMG_H / RPB;          // strips per image = 16
    const int n    = blockIdx.x / bpi;
    const int y0   = (blockIdx.x % bpi) * RPB;

    const float* Tn = T + (size_t)n * IMG_H * IMG_W;
    const float* Xn = X + (size_t)n * IMG_H * IMG_W;

    // ---- prologue: vertical running sums over rows [y0-15, y0+14] ----
    float vs0 = 0.f, vs1 = 0.f, vs2 = 0.f, vs3 = 0.f;
    for (int k = -KRAD; k < KRAD; ++k) {
        int yy = y0 + k;
        if (yy >= 0 && yy < IMG_H) {
            float4 v = *(const float4*)(Tn + yy * IMG_W + c0);
            vs0 += v.x; vs1 += v.y; vs2 += v.z; vs3 += v.w;
        }
    }

    float a0 = 0.f, a1 = 0.f, a2 = 0.f;

    #pragma unroll 1
    for (int y = y0; y < y0 + RPB; ++y) {
        const int pb = y & 1;

        // extend window: add row y+15  -> vs = sum rows [y-15, y+15]
        int ya = y + KRAD;
        if (ya < IMG_H) {
            float4 v = *(const float4*)(Tn + ya * IMG_W + c0);
            vs0 += v.x; vs1 += v.y; vs2 += v.z; vs3 += v.w;
        }

        // issue center loads early (independent of scan)
        float4 tx = *(const float4*)(Xn + y * IMG_W + c0);
        float4 tc = *(const float4*)(Tn + y * IMG_W + c0);

        // ---- per-thread prefix over 4 columns ----
        float p0 = vs0;
        float p1 = p0 + vs1;
        float p2 = p1 + vs2;
        float p3 = p2 + vs3;

        // ---- warp inclusive scan of thread sums ----
        float s = p3;
        #pragma unroll
        for (int off = 1; off < 32; off <<= 1) {
            float nb = __shfl_up_sync(0xffffffffu, s, off);
            if (lane >= off) s += nb;
        }
        float ex = s - p3;                 // exclusive within warp
        if (lane == 31) wsum[pb][wid] = s; // warp total
        __syncthreads();

        // ---- warp offsets (4 warps: direct sum, no second scan) ----
        float w0 = wsum[pb][0], w1 = wsum[pb][1], w2 = wsum[pb][2];
        float woff = (wid > 0 ? w0 : 0.f) + (wid > 1 ? w1 : 0.f) + (wid > 2 ? w2 : 0.f);
        float base = woff + ex;

        float4 Pq;
        Pq.x = base + p0; Pq.y = base + p1; Pq.z = base + p2; Pq.w = base + p3;
        *(float4*)&Psh[pb][c0] = Pq;
        __syncthreads();

        // ---- taps: ws[c] = P[min(c+15,511)] - (c>=16 ? P[c-16] : 0) ----
        float4 lo;
        if (tid >= 4) lo = *(const float4*)&Psh[pb][c0 - 16];
        else          lo = make_float4(0.f, 0.f, 0.f, 0.f);
        float h0 = Psh[pb][min(c0 + 15, IMG_W - 1)];
        float h1 = Psh[pb][min(c0 + 16, IMG_W - 1)];
        float h2 = Psh[pb][min(c0 + 17, IMG_W - 1)];
        float h3 = Psh[pb][min(c0 + 18, IMG_W - 1)];

        float ws[4] = { h0 - lo.x, h1 - lo.y, h2 - lo.z, h3 - lo.w };
        float tv[4] = { tc.x, tc.y, tc.z, tc.w };
        float xv[4] = { tx.x, tx.y, tx.z, tx.w };

        #pragma unroll
        for (int j = 0; j < 4; ++j) {
            float x = xv[j], t = tv[j];
            float ax  = fabsf(x);
            float e   = __expf(-ax);
            float l1p = __logf(1.0f + e);
            // bce = l1p - t*min(x,0) + (1-t)*max(x,0)
            float bce = l1p - t * fminf(x, 0.f) + (1.f - t) * fmaxf(x, 0.f);
            float rp  = __fdividef(1.0f, 1.0f + e);
            float p   = (x >= 0.f) ? rp : e * rp;

            float box  = ws[j] * INV_KK;
            float weit = 1.0f + 5.0f * fabsf(box - t);

            a0 += weit * bce;
            a1 += p * t * weit;
            a2 += (p + t) * weit;
        }

        // retire row y-15
        int ys = y - KRAD;
        if (ys >= 0) {
            float4 v = *(const float4*)(Tn + ys * IMG_W + c0);
            vs0 -= v.x; vs1 -= v.y; vs2 -= v.z; vs3 -= v.w;
        }
        // no trailing barrier: double-buffered smem
    }

    // ---- block reduction ----
    #pragma unroll
    for (int off = 16; off > 0; off >>= 1) {
        a0 += __shfl_down_sync(0xffffffffu, a0, off);
        a1 += __shfl_down_sync(0xffffffffu, a1, off);
        a2 += __shfl_down_sync(0xffffffffu, a2, off);
    }
    if (lane == 0) { red[wid][0] = a0; red[wid][1] = a1; red[wid][2] = a2; }
    __syncthreads();
    if (tid == 0) {
        float s0 = red[0][0] + red[1][0] + red[2][0] + red[3][0];
        float s1 = red[0][1] + red[1][1] + red[2][1] + red[3][1];
        float s2 = red[0][2] + red[1][2] + red[2][2] + red[3][2];
        g_part[0 * MAXB + blockIdx.x] = s0;
        g_part[1 * MAXB + blockIdx.x] = s1;
        g_part[2 * MAXB + blockIdx.x] = s2;
    }
}

__global__ __launch_bounds__(1024) void finalize_kernel(float* out, int nblocks, double inv_count) {
    __shared__ double sred[32][3];
    int tid  = threadIdx.x;
    int lane = tid & 31;
    int wid  = tid >> 5;

    double d0 = 0.0, d1 = 0.0, d2 = 0.0;
    for (int i = tid; i < nblocks; i += 1024) {
        d0 += (double)g_part[0 * MAXB + i];
        d1 += (double)g_part[1 * MAXB + i];
        d2 += (double)g_part[2 * MAXB + i];
    }
    #pragma unroll
    for (int off = 16; off > 0; off >>= 1) {
        d0 += __shfl_down_sync(0xffffffffu, d0, off);
        d1 += __shfl_down_sync(0xffffffffu, d1, off);
        d2 += __shfl_down_sync(0xffffffffu, d2, off);
    }
    if (lane == 0) { sred[wid][0] = d0; sred[wid][1] = d1; sred[wid][2] = d2; }
    __syncthreads();
    if (tid == 0) {
        double s0 = 0.0, s1 = 0.0, s2 = 0.0;
        #pragma unroll
        for (int i = 0; i < 32; ++i) { s0 += sred[i][0]; s1 += sred[i][1]; s2 += sred[i][2]; }
        double wbce  = s0 * inv_count;
        double uni   = s2 - s1;
        double wiou  = 1.0 - (s1 + 1.0) / (uni + 1.0);
        out[0] = (float)(wbce + wiou);
    }
}

extern "C" void kernel_launch(void* const* d_in, const int* in_sizes, int n_in,
                              void* d_out, int out_size) {
    const float* X = (const float*)d_in[0];
    const float* T = (const float*)d_in[1];
    float* out = (float*)d_out;

    const int n_elem = in_sizes[0];
    const int imgs   = n_elem / (IMG_H * IMG_W);
    const int bpi    = IMG_H / RPB;
    const int nb     = imgs * bpi;

    wiou_bce_main<<<nb, TPB>>>(X, T);
    finalize_kernel<<<1, 1024>>>(out, nb, 1.0 / (double)n_elem);
}

// round 3
// speedup vs baseline: 2.9650x; 1.0293x over previous
#include <cuda_runtime.h>

#define IMG_H 512
#define IMG_W 512
#define RPB   32
#define KRAD  15
#define INV_KK (1.0f/961.0f)
#define TPB   128
#define NW    4

__device__ double g_acc[3];
__device__ unsigned int g_count;

__global__ __launch_bounds__(TPB) void wiou_bce_main(
    const float* __restrict__ X,   // logits
    const float* __restrict__ T,   // targets
    float* __restrict__ out, int nblocks, double inv_count)
{
    // warp-private prefix buffers, double-buffered. Slo[li] = inclusive prefix S[li],
    // Shi[k] = S[k+31]  (so hi-taps are one aligned LDS.128).
    __shared__ alignas(16) float Slo[2][NW][160];
    __shared__ alignas(16) float Shi[2][NW][128];
    __shared__ float red[NW][3];

    const int tid  = threadIdx.x;
    const int lane = tid & 31;
    const int w    = tid >> 5;

    const int bpi = IMG_H / RPB;            // 16 strips per image
    const int n   = blockIdx.x / bpi;
    const int y0  = (blockIdx.x % bpi) * RPB;

    const float* Tn = T + (size_t)n * IMG_H * IMG_W;
    const float* Xn = X + (size_t)n * IMG_H * IMG_W;

    // scan columns: warp covers global cols [w*128-16, w*128+144), 5 per thread
    const int scol = w * 128 - 16 + lane * 5;
    bool val[5];
    #pragma unroll
    for (int j = 0; j < 5; ++j) val[j] = (scol + j) >= 0 && (scol + j) < IMG_W;
    // owned pixel columns: 4 per thread
    const int ccol = w * 128 + lane * 4;

    // ---- prologue: vertical running sums over rows [y0-15, y0+14] ----
    float vs[5] = {0.f, 0.f, 0.f, 0.f, 0.f};
    for (int k = -KRAD; k < KRAD; ++k) {
        int yy = y0 + k;
        if (yy >= 0 && yy < IMG_H) {
            const float* row = Tn + yy * IMG_W;
            #pragma unroll
            for (int j = 0; j < 5; ++j) if (val[j]) vs[j] += row[scol + j];
        }
    }

    float a0 = 0.f, a1 = 0.f, a2 = 0.f;

    #pragma unroll 1
    for (int y = y0; y < y0 + RPB; ++y) {
        const int pb = y & 1;

        // extend window: add row y+15  -> vs = rows [y-15, y+15]
        int ya = y + KRAD;
        if (ya < IMG_H) {
            const float* row = Tn + ya * IMG_W;
            #pragma unroll
            for (int j = 0; j < 5; ++j) if (val[j]) vs[j] += row[scol + j];
        }

        // center loads (independent of scan -> overlap)
        float4 xc = *(const float4*)(Xn + y * IMG_W + ccol);
        float4 tc = *(const float4*)(Tn + y * IMG_W + ccol);

        // ---- per-thread prefix over 5 scan cols ----
        float p[5];
        p[0] = vs[0];
        #pragma unroll
        for (int j = 1; j < 5; ++j) p[j] = p[j-1] + vs[j];

        // ---- warp inclusive scan of thread totals ----
        float s = p[4];
        #pragma unroll
        for (int off = 1; off < 32; off <<= 1) {
            float nb = __shfl_up_sync(0xffffffffu, s, off);
            if (lane >= off) s += nb;
        }
        float ex = s - p[4];

        // store prefix (stride-5 -> conflict-free) + shifted copy for hi taps
        #pragma unroll
        for (int j = 0; j < 5; ++j) {
            float Sv = ex + p[j];
            int li = lane * 5 + j;
            Slo[pb][w][li] = Sv;
            int li2 = li - 31;
            if (li2 >= 0 && li2 < 128) Shi[pb][w][li2] = Sv;
        }
        __syncwarp();

        // taps: ws[c] = S[c+31] - S[c]   (c = local owned col)
        float4 lo = *(const float4*)&Slo[pb][w][lane * 4];
        float4 hi = *(const float4*)&Shi[pb][w][lane * 4];

        float wsv[4] = { hi.x - lo.x, hi.y - lo.y, hi.z - lo.z, hi.w - lo.w };
        float xv[4]  = { xc.x, xc.y, xc.z, xc.w };
        float tv[4]  = { tc.x, tc.y, tc.z, tc.w };

        #pragma unroll
        for (int j = 0; j < 4; ++j) {
            float x = xv[j], t = tv[j];
            float ax  = fabsf(x);
            float e   = __expf(-ax);
            float l1p = __logf(1.0f + e);
            float bce = l1p - t * fminf(x, 0.f) + (1.f - t) * fmaxf(x, 0.f);
            float rp  = __fdividef(1.0f, 1.0f + e);
            float p_  = (x >= 0.f) ? rp : e * rp;

            float box  = wsv[j] * INV_KK;
            float weit = 1.0f + 5.0f * fabsf(box - t);

            a0 += weit * bce;
            a1 += p_ * t * weit;
            a2 += (p_ + t) * weit;
        }

        // retire row y-15
        int ys = y - KRAD;
        if (ys >= 0) {
            const float* row = Tn + ys * IMG_W;
            #pragma unroll
            for (int j = 0; j < 5; ++j) if (val[j]) vs[j] -= row[scol + j];
        }
        // no block barrier; double-buffered warp-private smem + per-row syncwarp
    }

    // ---- block reduction ----
    #pragma unroll
    for (int off = 16; off > 0; off >>= 1) {
        a0 += __shfl_down_sync(0xffffffffu, a0, off);
        a1 += __shfl_down_sync(0xffffffffu, a1, off);
        a2 += __shfl_down_sync(0xffffffffu, a2, off);
    }
    if (lane == 0) { red[w][0] = a0; red[w][1] = a1; red[w][2] = a2; }
    __syncthreads();

    if (tid == 0) {
        float s0 = red[0][0] + red[1][0] + red[2][0] + red[3][0];
        float s1 = red[0][1] + red[1][1] + red[2][1] + red[3][1];
        float s2 = red[0][2] + red[1][2] + red[2][2] + red[3][2];
        atomicAdd(&g_acc[0], (double)s0);
        atomicAdd(&g_acc[1], (double)s1);
        atomicAdd(&g_acc[2], (double)s2);
        __threadfence();
        unsigned int old = atomicAdd(&g_count, 1u);
        if (old == (unsigned int)(nblocks - 1)) {
            __threadfence();
            double d0 = g_acc[0], d1 = g_acc[1], d2 = g_acc[2];
            double wbce = d0 * inv_count;
            double uni  = d2 - d1;
            double wiou = 1.0 - (d1 + 1.0) / (uni + 1.0);
            out[0] = (float)(wbce + wiou);
            // reset for next graph replay
            g_acc[0] = 0.0; g_acc[1] = 0.0; g_acc[2] = 0.0;
            g_count = 0u;
        }
    }
}

extern "C" void kernel_launch(void* const* d_in, const int* in_sizes, int n_in,
                              void* d_out, int out_size) {
    const float* X = (const float*)d_in[0];
    const float* T = (const float*)d_in[1];
    float* out = (float*)d_out;

    const int n_elem = in_sizes[0];
    const int imgs   = n_elem / (IMG_H * IMG_W);
    const int nb     = imgs * (IMG_H / RPB);

    wiou_bce_main<<<nb, TPB>>>(X, T, out, nb, 1.0 / (double)n_elem);
}

// round 4
// speedup vs baseline: 3.3033x; 1.1141x over previous
#include <cuda_runtime.h>

#define IMG_H 512
#define IMG_W 512
#define RPB   16
#define KRAD  15
#define INV_KK (1.0f/961.0f)
#define TPB   128
#define NW    4

__device__ double g_acc[3];
__device__ unsigned int g_count;

// One row-step of the fused loop. CHKA: guard add-row (last strip).
// CHKR: guard retire-row (first strip).
#define ROW_BODY(CHKA, CHKR)                                                   \
  for (int r = 0; r < RPB; ++r) {                                              \
    const int pb = r & 1;                                                      \
    if (!(CHKA) || (y0 + r + KRAD) < IMG_H) {                                  \
      _Pragma("unroll")                                                        \
      for (int j = 0; j < 5; ++j) if (val[j]) vs[j] += pAdd[j];                \
    }                                                                          \
    float4 xc = *(const float4*)pX;                                            \
    float4 tc = *(const float4*)pT;                                            \
    float p[5];                                                                \
    p[0] = vs[0];                                                              \
    _Pragma("unroll")                                                          \
    for (int j = 1; j < 5; ++j) p[j] = p[j-1] + vs[j];                         \
    float s = p[4];                                                            \
    _Pragma("unroll")                                                          \
    for (int off = 1; off < 32; off <<= 1) {                                   \
      float nb = __shfl_up_sync(0xffffffffu, s, off);                          \
      if (lane >= off) s += nb;                                                \
    }                                                                          \
    float ex = s - p[4];                                                       \
    _Pragma("unroll")                                                          \
    for (int j = 0; j < 5; ++j) {                                              \
      float Sv = ex + p[j];                                                    \
      int li = lane * 5 + j;                                                   \
      Slo[pb][w][li] = Sv;                                                     \
      int li2 = li - 31;                                                       \
      if (li2 >= 0 && li2 < 128) Shi[pb][w][li2] = Sv;                         \
    }                                                                          \
    __syncwarp();                                                              \
    float4 lo = *(const float4*)&Slo[pb][w][lane * 4];                         \
    float4 hi = *(const float4*)&Shi[pb][w][lane * 4];                         \
    float wsv[4] = { hi.x - lo.x, hi.y - lo.y, hi.z - lo.z, hi.w - lo.w };     \
    float xv[4]  = { xc.x, xc.y, xc.z, xc.w };                                 \
    float tv[4]  = { tc.x, tc.y, tc.z, tc.w };                                 \
    _Pragma("unroll")                                                          \
    for (int j = 0; j < 4; ++j) {                                              \
      float x = xv[j], t = tv[j];                                              \
      float ax  = fabsf(x);                                                    \
      float e   = __expf(-ax);                                                 \
      float l1p = __logf(1.0f + e);                                            \
      float bce = l1p - t * fminf(x, 0.f) + (1.f - t) * fmaxf(x, 0.f);         \
      float rp  = __fdividef(1.0f, 1.0f + e);                                  \
      float p_  = (x >= 0.f) ? rp : e * rp;                                    \
      float box  = wsv[j] * INV_KK;                                            \
      float weit = 1.0f + 5.0f * fabsf(box - t);                               \
      a0 += weit * bce;                                                        \
      a1 += p_ * t * weit;                                                     \
      a2 += (p_ + t) * weit;                                                   \
    }                                                                          \
    if (!(CHKR) || (y0 + r - KRAD) >= 0) {                                     \
      _Pragma("unroll")                                                        \
      for (int j = 0; j < 5; ++j) if (val[j]) vs[j] -= pRet[j];                \
    }                                                                          \
    pAdd += IMG_W; pRet += IMG_W; pX += IMG_W; pT += IMG_W;                    \
  }

__global__ __launch_bounds__(TPB) void wiou_bce_main(
    const float* __restrict__ X,   // logits
    const float* __restrict__ T,   // targets
    float* __restrict__ out, int nblocks, double inv_count)
{
    __shared__ alignas(16) float Slo[2][NW][160];
    __shared__ alignas(16) float Shi[2][NW][128];
    __shared__ float red[NW][3];

    const int tid  = threadIdx.x;
    const int lane = tid & 31;
    const int w    = tid >> 5;

    const int bpi = IMG_H / RPB;            // 32 strips per image
    const int n   = blockIdx.x / bpi;
    const int y0  = (blockIdx.x % bpi) * RPB;

    const float* Tn = T + (size_t)n * IMG_H * IMG_W;
    const float* Xn = X + (size_t)n * IMG_H * IMG_W;

    // scan columns: warp covers [w*128-16, w*128+144), 5 per thread
    const int scol = w * 128 - 16 + lane * 5;
    bool val[5];
    #pragma unroll
    for (int j = 0; j < 5; ++j) val[j] = (scol + j) >= 0 && (scol + j) < IMG_W;
    const int ccol = w * 128 + lane * 4;     // owned pixel cols (float4)

    // ---- prologue: vertical running sums over rows [y0-15, y0+14] ----
    float vs[5] = {0.f, 0.f, 0.f, 0.f, 0.f};
    {
        int klo = (y0 - KRAD < 0) ? -y0 : -KRAD;
        int khi = (y0 + KRAD > IMG_H) ? (IMG_H - y0) : KRAD;  // exclusive
        const float* row = Tn + (size_t)(y0 + klo) * IMG_W + scol;
        for (int k = klo; k < khi; ++k) {
            #pragma unroll
            for (int j = 0; j < 5; ++j) if (val[j]) vs[j] += row[j];
            row += IMG_W;
        }
    }

    float a0 = 0.f, a1 = 0.f, a2 = 0.f;

    const float* pAdd = Tn + (ptrdiff_t)(y0 + KRAD) * IMG_W + scol;
    const float* pRet = Tn + (ptrdiff_t)(y0 - KRAD) * IMG_W + scol;
    const float* pX   = Xn + (ptrdiff_t)y0 * IMG_W + ccol;
    const float* pT   = Tn + (ptrdiff_t)y0 * IMG_W + ccol;

    if (y0 == 0) {
        ROW_BODY(false, true)
    } else if (y0 >= IMG_H - RPB - KRAD + 1) {
        ROW_BODY(true, false)
    } else {
        ROW_BODY(false, false)
    }

    // ---- block reduction ----
    #pragma unroll
    for (int off = 16; off > 0; off >>= 1) {
        a0 += __shfl_down_sync(0xffffffffu, a0, off);
        a1 += __shfl_down_sync(0xffffffffu, a1, off);
        a2 += __shfl_down_sync(0xffffffffu, a2, off);
    }
    if (lane == 0) { red[w][0] = a0; red[w][1] = a1; red[w][2] = a2; }
    __syncthreads();

    if (tid == 0) {
        float s0 = red[0][0] + red[1][0] + red[2][0] + red[3][0];
        float s1 = red[0][1] + red[1][1] + red[2][1] + red[3][1];
        float s2 = red[0][2] + red[1][2] + red[2][2] + red[3][2];
        atomicAdd(&g_acc[0], (double)s0);
        atomicAdd(&g_acc[1], (double)s1);
        atomicAdd(&g_acc[2], (double)s2);
        __threadfence();
        unsigned int old = atomicAdd(&g_count, 1u);
        if (old == (unsigned int)(nblocks - 1)) {
            __threadfence();
            double d0 = g_acc[0], d1 = g_acc[1], d2 = g_acc[2];
            double wbce = d0 * inv_count;
            double uni  = d2 - d1;
            double wiou = 1.0 - (d1 + 1.0) / (uni + 1.0);
            out[0] = (float)(wbce + wiou);
            g_acc[0] = 0.0; g_acc[1] = 0.0; g_acc[2] = 0.0;
            g_count = 0u;
        }
    }
}

extern "C" void kernel_launch(void* const* d_in, const int* in_sizes, int n_in,
                              void* d_out, int out_size) {
    const float* X = (const float*)d_in[0];
    const float* T = (const float*)d_in[1];
    float* out = (float*)d_out;

    const int n_elem = in_sizes[0];
    const int imgs   = n_elem / (IMG_H * IMG_W);
    const int nb     = imgs * (IMG_H / RPB);

    wiou_bce_main<<<nb, TPB>>>(X, T, out, nb, 1.0 / (double)n_elem);
}

// round 5
// speedup vs baseline: 3.4580x; 1.0468x over previous
#include <cuda_runtime.h>

#define IMG_H 512
#define IMG_W 512
#define RPB   16
#define KRAD  15
#define INV_KK (1.0f/961.0f)
#define TPB   128
#define NW    4
#define FULL  0xffffffffu

__device__ double g_acc[3];
__device__ unsigned int g_count;

// One row step. CHKA: guard add-row (last strip). CHKR: guard retire-row (first strip).
#define ROW_BODY(CHKA, CHKR)                                                    \
  for (int r = 0; r < RPB; ++r) {                                               \
    if (!(CHKA) || (y0 + r + KRAD) < IMG_H) {                                   \
      if (validA) { float4 v = *(const float4*)pAdd;                            \
        vsA0 += v.x; vsA1 += v.y; vsA2 += v.z; vsA3 += v.w; }                   \
      if (validB) { float4 v = *(const float4*)(pAdd + 128);                    \
        vsB0 += v.x; vsB1 += v.y; vsB2 += v.z; vsB3 += v.w; }                   \
    }                                                                           \
    float4 xc = *(const float4*)pX;                                             \
    float4 tc = *(const float4*)pT;                                             \
    /* per-chunk prefixes */                                                    \
    float qA0 = vsA0, qA1 = qA0 + vsA1, qA2 = qA1 + vsA2, qA3 = qA2 + vsA3;     \
    float qB0 = vsB0, qB1 = qB0 + vsB1, qB2 = qB1 + vsB2, qB3 = qB2 + vsB3;     \
    /* warp scan of A chunk totals */                                           \
    float sA = qA3;                                                             \
    _Pragma("unroll")                                                           \
    for (int off = 1; off < 32; off <<= 1) {                                    \
      float nb = __shfl_up_sync(FULL, sA, off);                                 \
      if (lane >= off) sA += nb;                                                \
    }                                                                           \
    float EA = sA - qA3;                                                        \
    float tot32 = __shfl_sync(FULL, sA, 31);                                    \
    /* 8-lane scan of B chunk totals (lanes 0..7 meaningful) */                 \
    float sB = qB3;                                                             \
    _Pragma("unroll")                                                           \
    for (int off = 1; off < 8; off <<= 1) {                                     \
      float nb = __shfl_up_sync(FULL, sB, off);                                 \
      if (lane >= off) sB += nb;                                                \
    }                                                                           \
    float EB = tot32 + (sB - qB3);                                              \
    /* inclusive prefix values owned by this thread */                          \
    float SA0 = EA + qA0, SA1 = EA + qA1, SA2 = EA + qA2, SA3 = EA + qA3;       \
    float SB0 = EB + qB0, SB1 = EB + qB1, SB2 = EB + qB2, SB3 = EB + qB3;       \
    /* hi taps S[4*lane+31+j] via shfl (wraps mod 32) */                        \
    float a3 = __shfl_sync(FULL, SA3, lane + 7);                                \
    float b3 = __shfl_sync(FULL, SB3, lane + 7);                                \
    float a0 = __shfl_sync(FULL, SA0, lane + 8);                                \
    float b0 = __shfl_sync(FULL, SB0, lane + 8);                                \
    float a1 = __shfl_sync(FULL, SA1, lane + 8);                                \
    float b1 = __shfl_sync(FULL, SB1, lane + 8);                                \
    float a2 = __shfl_sync(FULL, SA2, lane + 8);                                \
    float b2 = __shfl_sync(FULL, SB2, lane + 8);                                \
    float hi0 = (lane < 25) ? a3 : b3;                                          \
    float hi1 = (lane < 24) ? a0 : b0;                                          \
    float hi2 = (lane < 24) ? a1 : b1;                                          \
    float hi3 = (lane < 24) ? a2 : b2;                                          \
    float wsv[4] = { hi0 - SA0, hi1 - SA1, hi2 - SA2, hi3 - SA3 };              \
    float xv[4]  = { xc.x, xc.y, xc.z, xc.w };                                  \
    float tv[4]  = { tc.x, tc.y, tc.z, tc.w };                                  \
    _Pragma("unroll")                                                           \
    for (int j = 0; j < 4; ++j) {                                               \
      float x = xv[j], t = tv[j];                                               \
      float ax  = fabsf(x);                                                     \
      float e   = __expf(-ax);                                                  \
      float l1p = __logf(1.0f + e);                                             \
      float bce = l1p - t * fminf(x, 0.f) + (1.f - t) * fmaxf(x, 0.f);          \
      float rp  = __fdividef(1.0f, 1.0f + e);                                   \
      float p_  = (x >= 0.f) ? rp : e * rp;                                     \
      float box  = wsv[j] * INV_KK;                                             \
      float weit = 1.0f + 5.0f * fabsf(box - t);                                \
      a0_ += weit * bce;                                                        \
      a1_ += p_ * t * weit;                                                     \
      a2_ += (p_ + t) * weit;                                                   \
    }                                                                           \
    if (!(CHKR) || (y0 + r - KRAD) >= 0) {                                      \
      if (validA) { float4 v = *(const float4*)pRet;                            \
        vsA0 -= v.x; vsA1 -= v.y; vsA2 -= v.z; vsA3 -= v.w; }                   \
      if (validB) { float4 v = *(const float4*)(pRet + 128);                    \
        vsB0 -= v.x; vsB1 -= v.y; vsB2 -= v.z; vsB3 -= v.w; }                   \
    }                                                                           \
    pAdd += IMG_W; pRet += IMG_W; pX += IMG_W; pT += IMG_W;                     \
  }

__global__ __launch_bounds__(TPB) void wiou_bce_main(
    const float* __restrict__ X,   // logits
    const float* __restrict__ T,   // targets
    float* __restrict__ out, int nblocks, double inv_count)
{
    __shared__ float red[NW][3];

    const int tid  = threadIdx.x;
    const int lane = tid & 31;
    const int w    = tid >> 5;

    const int bpi = IMG_H / RPB;            // 32 strips per image
    const int n   = blockIdx.x / bpi;
    const int y0  = (blockIdx.x % bpi) * RPB;

    const float* Tn = T + (size_t)n * IMG_H * IMG_W;
    const float* Xn = X + (size_t)n * IMG_H * IMG_W;

    // scan window: local u in [0,160), global col = w*128 - 16 + u
    // chunk A = u[4*lane .. +3] (all lanes), chunk B = u[128+4*lane .. +3] (lanes 0..7)
    const int colA = w * 128 - 16 + lane * 4;
    const bool validA = !(w == 0 && lane < 4);
    const bool validB = (lane < 8) && !(w == 3 && lane >= 4);
    const int ccol = w * 128 + lane * 4;    // owned pixel cols (float4)

    // ---- prologue: vertical sums over rows [y0-15, y0+14] ----
    float vsA0 = 0.f, vsA1 = 0.f, vsA2 = 0.f, vsA3 = 0.f;
    float vsB0 = 0.f, vsB1 = 0.f, vsB2 = 0.f, vsB3 = 0.f;
    {
        int klo = (y0 - KRAD < 0) ? 0 : (y0 - KRAD);
        const float* row = Tn + (ptrdiff_t)klo * IMG_W + colA;
        for (int yy = klo; yy <= y0 + KRAD - 1; ++yy) {
            if (validA) { float4 v = *(const float4*)row;
                vsA0 += v.x; vsA1 += v.y; vsA2 += v.z; vsA3 += v.w; }
            if (validB) { float4 v = *(const float4*)(row + 128);
                vsB0 += v.x; vsB1 += v.y; vsB2 += v.z; vsB3 += v.w; }
            row += IMG_W;
        }
    }

    float a0_ = 0.f, a1_ = 0.f, a2_ = 0.f;

    const float* pAdd = Tn + (ptrdiff_t)(y0 + KRAD) * IMG_W + colA;
    const float* pRet = Tn + (ptrdiff_t)(y0 - KRAD) * IMG_W + colA;
    const float* pX   = Xn + (ptrdiff_t)y0 * IMG_W + ccol;
    const float* pT   = Tn + (ptrdiff_t)y0 * IMG_W + ccol;

    if (y0 == 0) {
        ROW_BODY(false, true)
    } else if (y0 >= IMG_H - RPB - KRAD + 1) {
        ROW_BODY(true, false)
    } else {
        ROW_BODY(false, false)
    }

    // ---- block reduction ----
    #pragma unroll
    for (int off = 16; off > 0; off >>= 1) {
        a0_ += __shfl_down_sync(FULL, a0_, off);
        a1_ += __shfl_down_sync(FULL, a1_, off);
        a2_ += __shfl_down_sync(FULL, a2_, off);
    }
    if (lane == 0) { red[w][0] = a0_; red[w][1] = a1_; red[w][2] = a2_; }
    __syncthreads();

    if (tid == 0) {
        float s0 = red[0][0] + red[1][0] + red[2][0] + red[3][0];
        float s1 = red[0][1] + red[1][1] + red[2][1] + red[3][1];
        float s2 = red[0][2] + red[1][2] + red[2][2] + red[3][2];
        atomicAdd(&g_acc[0], (double)s0);
        atomicAdd(&g_acc[1], (double)s1);
        atomicAdd(&g_acc[2], (double)s2);
        __threadfence();
        unsigned int old = atomicAdd(&g_count, 1u);
        if (old == (unsigned int)(nblocks - 1)) {
            __threadfence();
            double d0 = g_acc[0], d1 = g_acc[1], d2 = g_acc[2];
            double wbce = d0 * inv_count;
            double uni  = d2 - d1;
            double wiou = 1.0 - (d1 + 1.0) / (uni + 1.0);
            out[0] = (float)(wbce + wiou);
            g_acc[0] = 0.0; g_acc[1] = 0.0; g_acc[2] = 0.0;
            g_count = 0u;
        }
    }
}

extern "C" void kernel_launch(void* const* d_in, const int* in_sizes, int n_in,
                              void* d_out, int out_size) {
    const float* X = (const float*)d_in[0];
    const float* T = (const float*)d_in[1];
    float* out = (float*)d_out;

    const int n_elem = in_sizes[0];
    const int imgs   = n_elem / (IMG_H * IMG_W);
    const int nb     = imgs * (IMG_H / RPB);

    wiou_bce_main<<<nb, TPB>>>(X, T, out, nb, 1.0 / (double)n_elem);
}

// round 6
// speedup vs baseline: 3.8742x; 1.1204x over previous
#include <cuda_runtime.h>

#define IMG_H 512
#define IMG_W 512
#define RPB   32
#define KRAD  15
#define INV_KK (1.0f/961.0f)
#define TPB   128
#define NW    4
#define FULL  0xffffffffu

__device__ double g_acc[3];
__device__ unsigned int g_count;

struct V8 { float a0,a1,a2,a3,b0,b1,b2,b3; };

__device__ __forceinline__ void addv(V8& s, const float* pA, bool vA, bool vB, float sgn) {
    if (vA) { float4 v = *(const float4*)pA;
        s.a0 += sgn*v.x; s.a1 += sgn*v.y; s.a2 += sgn*v.z; s.a3 += sgn*v.w; }
    if (vB) { float4 v = *(const float4*)(pA + 128);
        s.b0 += sgn*v.x; s.b1 += sgn*v.y; s.b2 += sgn*v.z; s.b3 += sgn*v.w; }
}

// scan 160 cols held as chunk A (all lanes) + chunk B (lanes 0..7), produce
// box sums for the 4 owned cols, run the elementwise math, accumulate.
__device__ __forceinline__ void scan_and_accum(
    const V8 vs, float4 xc, float4 tc, int lane,
    float& r0, float& r1, float& r2)
{
    float qA0 = vs.a0, qA1 = qA0 + vs.a1, qA2 = qA1 + vs.a2, qA3 = qA2 + vs.a3;
    float qB0 = vs.b0, qB1 = qB0 + vs.b1, qB2 = qB1 + vs.b2, qB3 = qB2 + vs.b3;

    float sA = qA3;
    #pragma unroll
    for (int off = 1; off < 32; off <<= 1) {
        float nb = __shfl_up_sync(FULL, sA, off);
        if (lane >= off) sA += nb;
    }
    float EA = sA - qA3;
    float tot32 = __shfl_sync(FULL, sA, 31);

    float sB = qB3;
    #pragma unroll
    for (int off = 1; off < 8; off <<= 1) {
        float nb = __shfl_up_sync(FULL, sB, off);
        if (lane >= off) sB += nb;
    }
    float EB = tot32 + (sB - qB3);

    float SA0 = EA + qA0, SA1 = EA + qA1, SA2 = EA + qA2, SA3 = EA + qA3;
    float SB0 = EB + qB0, SB1 = EB + qB1, SB2 = EB + qB2, SB3 = EB + qB3;

    float a3 = __shfl_sync(FULL, SA3, lane + 7);
    float b3 = __shfl_sync(FULL, SB3, lane + 7);
    float a0 = __shfl_sync(FULL, SA0, lane + 8);
    float b0 = __shfl_sync(FULL, SB0, lane + 8);
    float a1 = __shfl_sync(FULL, SA1, lane + 8);
    float b1 = __shfl_sync(FULL, SB1, lane + 8);
    float a2 = __shfl_sync(FULL, SA2, lane + 8);
    float b2 = __shfl_sync(FULL, SB2, lane + 8);
    float hi0 = (lane < 25) ? a3 : b3;
    float hi1 = (lane < 24) ? a0 : b0;
    float hi2 = (lane < 24) ? a1 : b1;
    float hi3 = (lane < 24) ? a2 : b2;

    float wsv[4] = { hi0 - SA0, hi1 - SA1, hi2 - SA2, hi3 - SA3 };
    float xv[4]  = { xc.x, xc.y, xc.z, xc.w };
    float tv[4]  = { tc.x, tc.y, tc.z, tc.w };

    #pragma unroll
    for (int j = 0; j < 4; ++j) {
        float x = xv[j], t = tv[j];
        float ax  = fabsf(x);
        float e   = __expf(-ax);
        float l1p = __logf(1.0f + e);
        float bce = l1p - t * fminf(x, 0.f) + (1.f - t) * fmaxf(x, 0.f);
        float rp  = __fdividef(1.0f, 1.0f + e);
        float p_  = (x >= 0.f) ? rp : e * rp;
        float box  = wsv[j] * INV_KK;
        float weit = 1.0f + 5.0f * fabsf(box - t);
        r0 += weit * bce;
        r1 += p_ * t * weit;
        r2 += (p_ + t) * weit;
    }
}

__global__ __launch_bounds__(TPB, 7) void wiou_bce_main(
    const float* __restrict__ X,   // logits
    const float* __restrict__ T,   // targets
    float* __restrict__ out, int nblocks, double inv_count)
{
    __shared__ float red[NW][3];

    const int tid  = threadIdx.x;
    const int lane = tid & 31;
    const int w    = tid >> 5;

    const int bpi = IMG_H / RPB;            // 16 strips per image
    const int n   = blockIdx.x / bpi;
    const int y0  = (blockIdx.x % bpi) * RPB;

    const float* Tn = T + (size_t)n * IMG_H * IMG_W;
    const float* Xn = X + (size_t)n * IMG_H * IMG_W;

    const int colA = w * 128 - 16 + lane * 4;
    const bool validA = !(w == 0 && lane < 4);
    const bool validB = (lane < 8) && !(w == 3 && lane >= 4);
    const int ccol = w * 128 + lane * 4;

    // ---- prologue: vertical sums over rows [y0-15, y0+14] ----
    V8 vs = {0.f,0.f,0.f,0.f, 0.f,0.f,0.f,0.f};
    {
        int klo = (y0 - KRAD < 0) ? 0 : (y0 - KRAD);
        const float* row = Tn + (ptrdiff_t)klo * IMG_W + colA;
        for (int yy = klo; yy <= y0 + KRAD - 1; ++yy) {
            addv(vs, row, validA, validB, 1.0f);
            row += IMG_W;
        }
    }

    float r0 = 0.f, r1 = 0.f, r2 = 0.f;

    const float* pAdd = Tn + (ptrdiff_t)(y0 + KRAD) * IMG_W + colA;   // row y+15
    const float* pRet = Tn + (ptrdiff_t)(y0 - KRAD) * IMG_W + colA;   // row y-15
    const float* pX   = Xn + (ptrdiff_t)y0 * IMG_W + ccol;
    const float* pT   = Tn + (ptrdiff_t)y0 * IMG_W + ccol;

    #pragma unroll 1
    for (int r = 0; r < RPB; r += 2) {
        const int y = y0 + r;
        const bool ga1 = (y + KRAD)     < IMG_H;
        const bool ga2 = (y + KRAD + 1) < IMG_H;
        const bool gr1 = (y - KRAD)     >= 0;
        const bool gr2 = (y - KRAD + 1) >= 0;

        // center loads for both rows (independent, issued early)
        float4 xc1 = *(const float4*)pX;
        float4 tc1 = *(const float4*)pT;
        float4 xc2 = *(const float4*)(pX + IMG_W);
        float4 tc2 = *(const float4*)(pT + IMG_W);

        // row y
        addv(vs, pAdd, validA && ga1, validB && ga1, 1.0f);
        V8 vs1 = vs;
        scan_and_accum(vs1, xc1, tc1, lane, r0, r1, r2);

        // row y+1
        addv(vs1, pAdd + IMG_W, validA && ga2, validB && ga2, 1.0f);
        addv(vs1, pRet,         validA && gr1, validB && gr1, -1.0f);
        scan_and_accum(vs1, xc2, tc2, lane, r0, r1, r2);

        // retire for next iteration
        addv(vs1, pRet + IMG_W, validA && gr2, validB && gr2, -1.0f);
        vs = vs1;

        pAdd += 2 * IMG_W; pRet += 2 * IMG_W; pX += 2 * IMG_W; pT += 2 * IMG_W;
    }

    // ---- block reduction ----
    #pragma unroll
    for (int off = 16; off > 0; off >>= 1) {
        r0 += __shfl_down_sync(FULL, r0, off);
        r1 += __shfl_down_sync(FULL, r1, off);
        r2 += __shfl_down_sync(FULL, r2, off);
    }
    if (lane == 0) { red[w][0] = r0; red[w][1] = r1; red[w][2] = r2; }
    __syncthreads();

    if (tid == 0) {
        float s0 = red[0][0] + red[1][0] + red[2][0] + red[3][0];
        float s1 = red[0][1] + red[1][1] + red[2][1] + red[3][1];
        float s2 = red[0][2] + red[1][2] + red[2][2] + red[3][2];
        atomicAdd(&g_acc[0], (double)s0);
        atomicAdd(&g_acc[1], (double)s1);
        atomicAdd(&g_acc[2], (double)s2);
        __threadfence();
        unsigned int old = atomicAdd(&g_count, 1u);
        if (old == (unsigned int)(nblocks - 1)) {
            __threadfence();
            double d0 = g_acc[0], d1 = g_acc[1], d2 = g_acc[2];
            double wbce = d0 * inv_count;
            double uni  = d2 - d1;
            double wiou = 1.0 - (d1 + 1.0) / (uni + 1.0);
            out[0] = (float)(wbce + wiou);
            g_acc[0] = 0.0; g_acc[1] = 0.0; g_acc[2] = 0.0;
            g_count = 0u;
        }
    }
}

extern "C" void kernel_launch(void* const* d_in, const int* in_sizes, int n_in,
                              void* d_out, int out_size) {
    const float* X = (const float*)d_in[0];
    const float* T = (const float*)d_in[1];
    float* out = (float*)d_out;

    const int n_elem = in_sizes[0];
    const int imgs   = n_elem / (IMG_H * IMG_W);
    const int nb     = imgs * (IMG_H / RPB);

    wiou_bce_main<<<nb, TPB>>>(X, T, out, nb, 1.0 / (double)n_elem);
}